// round 14
// baseline (speedup 1.0000x reference)
#include <cuda_runtime.h>

// Gibbs sweep over DIM=32 coordinates of B rows (triangular form).
// x_new = fwd_subst(I-L) of (base + U x_old); A = -P_ij/P_ii (diag 0).
// U/L zero-masked float4 columns in __constant__.
//
// R14 = R11 structure x 2 rows/thread: every A-column LDC.128 is shared by
// two independent row chains -> per-SM constant-port traffic halves (the
// LDC rt=8 floor was the R11 binder). State = 2x r only (64 regs), fits
// under the 96-reg cap without the old reduction-form accumulator pressure.

#define DIM 32
#define THREADS 128
#define ROWS_PER_BLOCK 256          // 2 rows per thread

__device__   float  g_T[2 * DIM * DIM];  // [0..1023] upper-masked, [1024..] lower-masked
__device__   float  g_SM[2 * DIM];       // [0..31] sigma, [32..63] mu
__constant__ float4 c_T4[2 * DIM * 8];   // col j: c_T4[j*8+q] (U), c_T4[256+j*8+q] (L)

__global__ void prep_kernel(const float* __restrict__ P,
                            const float* __restrict__ mu)
{
    int e = threadIdx.x;                 // 1024 threads
    int j = e >> 5, k = e & 31;          // column j, row k
    float a = -P[k * DIM + j] / P[k * DIM + k];   // A[k][j]
    g_T[e]              = (k < j) ? a : 0.0f;     // strict upper
    g_T[DIM * DIM + e]  = (k > j) ? a : 0.0f;     // strict lower
    if (e < DIM) {
        g_SM[e]       = sqrtf(1.0f / P[e * DIM + e]);
        g_SM[DIM + e] = mu[e];
    }
}

__device__ __forceinline__ unsigned long long f2u(float2 v) {
    unsigned long long u; __builtin_memcpy(&u, &v, 8); return u;
}
__device__ __forceinline__ float2 u2f(unsigned long long u) {
    float2 v; __builtin_memcpy(&v, &u, 8); return v;
}
__device__ __forceinline__ float2 ffma2(float2 a, float2 b, float2 c) {
    unsigned long long d;
    asm("fma.rn.f32x2 %0, %1, %2, %3;"
        : "=l"(d) : "l"(f2u(a)), "l"(f2u(b)), "l"(f2u(c)));
    return u2f(d);
}

__global__ __launch_bounds__(THREADS, 5)
void gibbs_sweep_kernel(const float* __restrict__ x,
                        const float* __restrict__ noise,
                        float* __restrict__ out,
                        int B)
{
    __shared__ float sgf[DIM];
    __shared__ float muf[DIM];
    // pad-33 scalar buffer for 256 rows (33.8 KB), reused:
    //  (1) base stage -> r regs   (2) x_old stage -> phase-1 scalars
    //  (3) swizzled float4 out-stage (16 KB region)
    __shared__ __align__(16) float buf[ROWS_PER_BLOCK * 33];

    const int tid = threadIdx.x;

    if (tid < DIM) { sgf[tid] = g_SM[tid]; muf[tid] = g_SM[DIM + tid]; }
    __syncthreads();

    const int R0 = blockIdx.x * ROWS_PER_BLOCK;

    // ---- stage base = mu + sigma*noise into pad-33 (coalesced LDG.128) ----
    const float4* gn = (const float4*)noise;
    #pragma unroll
    for (int k = 0; k < 16; ++k) {
        int idx = k * THREADS + tid;           // 0..2047, coalesced
        int row = idx >> 3;
        int c   = idx & 7;
        int gr  = R0 + row;
        float4 n4 = (gr < B) ? gn[(size_t)gr * 8 + c]
                             : make_float4(0.f, 0.f, 0.f, 0.f);
        float* d = buf + row * 33 + c * 4;
        d[0] = fmaf(sgf[c * 4 + 0], n4.x, muf[c * 4 + 0]);
        d[1] = fmaf(sgf[c * 4 + 1], n4.y, muf[c * 4 + 1]);
        d[2] = fmaf(sgf[c * 4 + 2], n4.z, muf[c * 4 + 2]);
        d[3] = fmaf(sgf[c * 4 + 3], n4.w, muf[c * 4 + 3]);
    }
    __syncthreads();

    // ---- r1/r2 <- base rows tid and tid+128 (conflict-free scalar LDS) ----
    const float* myrow1 = buf + tid * 33;
    const float* myrow2 = buf + (tid + THREADS) * 33;
    float2 r1[16], r2[16];
    #pragma unroll
    for (int j = 0; j < 16; ++j) {
        r1[j] = make_float2(myrow1[2 * j], myrow1[2 * j + 1]);
        r2[j] = make_float2(myrow2[2 * j], myrow2[2 * j + 1]);
    }
    __syncthreads();

    // ---- stage x_old into pad-33 ----
    const float4* gx = (const float4*)x;
    #pragma unroll
    for (int k = 0; k < 16; ++k) {
        int idx = k * THREADS + tid;
        int row = idx >> 3;
        int c   = idx & 7;
        int gr  = R0 + row;
        float4 v = (gr < B) ? gx[(size_t)gr * 8 + c]
                            : make_float4(0.f, 0.f, 0.f, 0.f);
        float* d = buf + row * 33 + c * 4;
        d[0] = v.x; d[1] = v.y; d[2] = v.z; d[3] = v.w;
    }
    __syncthreads();

    // ---- Phase 1: r += U x_old; each col LDC.128 feeds BOTH rows ----
    #pragma unroll
    for (int j = 1; j < DIM; ++j) {
        float xa = myrow1[j];
        float xb = myrow2[j];
        float2 xs1 = make_float2(xa, xa);
        float2 xs2 = make_float2(xb, xb);
        #pragma unroll
        for (int q = 0; q < ((j + 3) >> 2); ++q) {
            float4 col = c_T4[j * 8 + q];      // masked: k>=j zero
            float2 c0 = make_float2(col.x, col.y);
            float2 c1 = make_float2(col.z, col.w);
            r1[2 * q]     = ffma2(xs1, c0, r1[2 * q]);
            r1[2 * q + 1] = ffma2(xs1, c1, r1[2 * q + 1]);
            r2[2 * q]     = ffma2(xs2, c0, r2[2 * q]);
            r2[2 * q + 1] = ffma2(xs2, c1, r2[2 * q + 1]);
        }
    }

    // ---- Phase 2: forward substitution; shared col, two chains ----
    #pragma unroll
    for (int j = 0; j < DIM - 1; ++j) {
        float xa = (j & 1) ? r1[j >> 1].y : r1[j >> 1].x;
        float xb = (j & 1) ? r2[j >> 1].y : r2[j >> 1].x;
        float2 xs1 = make_float2(xa, xa);
        float2 xs2 = make_float2(xb, xb);
        #pragma unroll
        for (int q = j >> 2; q < 8; ++q) {
            float4 col = c_T4[256 + j * 8 + q]; // masked: k<=j zero
            float2 c0 = make_float2(col.x, col.y);
            float2 c1 = make_float2(col.z, col.w);
            r1[2 * q]     = ffma2(xs1, c0, r1[2 * q]);
            r1[2 * q + 1] = ffma2(xs1, c1, r1[2 * q + 1]);
            r2[2 * q]     = ffma2(xs2, c0, r2[2 * q]);
            r2[2 * q + 1] = ffma2(xs2, c1, r2[2 * q + 1]);
        }
    }

    __syncthreads();   // all x_old reads done before reusing buf
    // ---- scatter rows to swizzled float4 stage, then coalesced STG.128 ----
    float4* st4 = (float4*)buf;
    const int sw = (tid >> 2) & 7;
    #pragma unroll
    for (int c = 0; c < 8; ++c) {
        st4[tid * 8 + (c ^ sw)] =
            make_float4(r1[2 * c].x, r1[2 * c].y, r1[2 * c + 1].x, r1[2 * c + 1].y);
        st4[(tid + THREADS) * 8 + (c ^ sw)] =
            make_float4(r2[2 * c].x, r2[2 * c].y, r2[2 * c + 1].x, r2[2 * c + 1].y);
    }
    __syncthreads();
    float4* gout = (float4*)out;
    #pragma unroll
    for (int k = 0; k < 16; ++k) {
        int idx = k * THREADS + tid;
        int row = idx >> 3;
        int c   = idx & 7;
        int gr  = R0 + row;
        if (gr < B) gout[(size_t)gr * 8 + c] = st4[row * 8 + (c ^ ((row >> 2) & 7))];
    }
}

extern "C" void kernel_launch(void* const* d_in, const int* in_sizes, int n_in,
                              void* d_out, int out_size)
{
    const float* x     = (const float*)d_in[0];
    const float* noise = (const float*)d_in[1];
    const float* P     = (const float*)d_in[2];
    const float* mu    = (const float*)d_in[3];
    float* out = (float*)d_out;

    int B = in_sizes[0] / DIM;

    // 1) build masked column tables + sigma/mu on device
    prep_kernel<<<1, DIM * DIM>>>(P, mu);

    // 2) D2D copy to __constant__ (graph-capturable memcpy node)
    void* gT_addr = nullptr;
    cudaGetSymbolAddress(&gT_addr, g_T);
    cudaMemcpyToSymbolAsync(c_T4, gT_addr, sizeof(float) * 2 * DIM * DIM, 0,
                            cudaMemcpyDeviceToDevice, 0);

    // 3) the sweep
    int grid = (B + ROWS_PER_BLOCK - 1) / ROWS_PER_BLOCK;
    gibbs_sweep_kernel<<<grid, THREADS>>>(x, noise, out, B);
}